// round 2
// baseline (speedup 1.0000x reference)
#include <cuda_runtime.h>
#include <cstdint>

#define SEQ   4096
#define DIM   64
#define NBH   16          // B*H = 2*8
#define QB    64
#define KB    64
#define SCALE 0.125f      // 1/sqrt(64)

// Row-sum scratch (allocation-free per harness rules).
__device__ float g_invsum[NBH * SEQ];

__device__ __forceinline__ unsigned f2tf32(float f) {
    unsigned u;
    asm("cvt.rna.tf32.f32 %0, %1;" : "=r"(u) : "f"(f));
    return u;
}

__device__ __forceinline__ void mma_tf32(float c[4], const unsigned a[4],
                                         unsigned b0, unsigned b1) {
    asm volatile(
        "mma.sync.aligned.m16n8k8.row.col.f32.tf32.tf32.f32 "
        "{%0,%1,%2,%3}, {%4,%5,%6,%7}, {%8,%9}, {%0,%1,%2,%3};\n"
        : "+f"(c[0]), "+f"(c[1]), "+f"(c[2]), "+f"(c[3])
        : "r"(a[0]), "r"(a[1]), "r"(a[2]), "r"(a[3]), "r"(b0), "r"(b1));
}

// ===========================================================================
// Kernel 1: P = exp(mask ? scale*Q@K^T : -inf)  (unnormalized), row sums.
// Each CTA: 64 queries x ALL 4096 keys (so it owns complete rows -> exact
// row sums without atomics). 128 threads = 4 warps; warp w computes the
// 16x64 strip rows [16w, 16w+16).
// ===========================================================================
__global__ __launch_bounds__(128) void qk_exp_kernel(
    const float* __restrict__ Q, const float* __restrict__ Km,
    const int* __restrict__ mask, float* __restrict__ P)
{
    const int bh = blockIdx.y;
    const int q0 = blockIdx.x * QB;
    const float* Qp = Q + ((size_t)bh * SEQ + q0) * DIM;
    const float* Kp = Km + (size_t)bh * SEQ * DIM;
    float* Pp = P + ((size_t)bh * SEQ + q0) * SEQ;

    __shared__ float Qs[QB][DIM + 4];
    __shared__ float Ks[KB][DIM + 4];

    const int tid  = threadIdx.x;
    const int warp = tid >> 5;
    const int lane = tid & 31;
    const int gr   = lane >> 2;   // groupID (row within mma tile)
    const int lc   = lane & 3;    // thread-in-group (col)

    // Load Q tile once, pre-scaled, rounded to tf32.
    for (int i = tid; i < QB * (DIM / 4); i += 128) {
        int r = i >> 4, c4 = (i & 15) << 2;
        float4 v = *reinterpret_cast<const float4*>(Qp + (size_t)r * DIM + c4);
        Qs[r][c4 + 0] = __uint_as_float(f2tf32(v.x * SCALE));
        Qs[r][c4 + 1] = __uint_as_float(f2tf32(v.y * SCALE));
        Qs[r][c4 + 2] = __uint_as_float(f2tf32(v.z * SCALE));
        Qs[r][c4 + 3] = __uint_as_float(f2tf32(v.w * SCALE));
    }
    __syncthreads();

    // Hoist all A fragments (Q) for the 8 k-steps of D=64.
    unsigned a[8][4];
#pragma unroll
    for (int ds = 0; ds < 8; ds++) {
        a[ds][0] = __float_as_uint(Qs[warp * 16 + gr    ][ds * 8 + lc    ]);
        a[ds][1] = __float_as_uint(Qs[warp * 16 + gr + 8][ds * 8 + lc    ]);
        a[ds][2] = __float_as_uint(Qs[warp * 16 + gr    ][ds * 8 + lc + 4]);
        a[ds][3] = __float_as_uint(Qs[warp * 16 + gr + 8][ds * 8 + lc + 4]);
    }

    float rs0 = 0.f, rs1 = 0.f;   // row sums for rows (warp*16+gr) and (+8)
    const int qg0 = q0 + warp * 16 + gr;   // global query row

    for (int kt = 0; kt < SEQ / KB; kt++) {
        __syncthreads();
        const float* Kt = Kp + (size_t)kt * KB * DIM;
        for (int i = tid; i < KB * (DIM / 4); i += 128) {
            int r = i >> 4, c4 = (i & 15) << 2;
            float4 v = *reinterpret_cast<const float4*>(Kt + (size_t)r * DIM + c4);
            Ks[r][c4 + 0] = __uint_as_float(f2tf32(v.x));
            Ks[r][c4 + 1] = __uint_as_float(f2tf32(v.y));
            Ks[r][c4 + 2] = __uint_as_float(f2tf32(v.z));
            Ks[r][c4 + 3] = __uint_as_float(f2tf32(v.w));
        }
        __syncthreads();

        float c[8][4];
#pragma unroll
        for (int nt = 0; nt < 8; nt++) { c[nt][0] = c[nt][1] = c[nt][2] = c[nt][3] = 0.f; }

#pragma unroll
        for (int ds = 0; ds < 8; ds++) {
#pragma unroll
            for (int nt = 0; nt < 8; nt++) {
                // B fragment (col-major, 8x8): b0 = B[lc][gr] = K[nt*8+gr][ds*8+lc]
                unsigned b0 = __float_as_uint(Ks[nt * 8 + gr][ds * 8 + lc    ]);
                unsigned b1 = __float_as_uint(Ks[nt * 8 + gr][ds * 8 + lc + 4]);
                mma_tf32(c[nt], a[ds], b0, b1);
            }
        }

        // Epilogue: mask, exp, write unnormalized P, accumulate row sums.
#pragma unroll
        for (int nt = 0; nt < 8; nt++) {
            int col = kt * KB + nt * 8 + lc * 2;
            int2 m0 = *reinterpret_cast<const int2*>(mask + (size_t)qg0 * SEQ + col);
            int2 m1 = *reinterpret_cast<const int2*>(mask + (size_t)(qg0 + 8) * SEQ + col);
            float p0 = m0.x ? __expf(c[nt][0]) : 0.f;
            float p1 = m0.y ? __expf(c[nt][1]) : 0.f;
            float p2 = m1.x ? __expf(c[nt][2]) : 0.f;
            float p3 = m1.y ? __expf(c[nt][3]) : 0.f;
            rs0 += p0 + p1;
            rs1 += p2 + p3;
            *reinterpret_cast<float2*>(Pp + (size_t)(warp * 16 + gr) * SEQ + col) =
                make_float2(p0, p1);
            *reinterpret_cast<float2*>(Pp + (size_t)(warp * 16 + gr + 8) * SEQ + col) =
                make_float2(p2, p3);
        }
    }

    // Reduce row sums across the 4 threads sharing each row.
    rs0 += __shfl_xor_sync(0xffffffffu, rs0, 1);
    rs0 += __shfl_xor_sync(0xffffffffu, rs0, 2);
    rs1 += __shfl_xor_sync(0xffffffffu, rs1, 1);
    rs1 += __shfl_xor_sync(0xffffffffu, rs1, 2);
    if (lc == 0) {
        g_invsum[bh * SEQ + q0 + warp * 16 + gr    ] = 1.f / rs0;
        g_invsum[bh * SEQ + q0 + warp * 16 + gr + 8] = 1.f / rs1;
    }
}

// ===========================================================================
// Kernel 2: normalize P in place (final attention output) and O = Pn @ V.
// Same tiling: CTA = 64 queries x all keys.
// ===========================================================================
__global__ __launch_bounds__(128) void av_kernel(
    const float* __restrict__ V, float* __restrict__ P, float* __restrict__ O)
{
    const int bh = blockIdx.y;
    const int q0 = blockIdx.x * QB;
    float* Pp = P + ((size_t)bh * SEQ + q0) * SEQ;
    const float* Vp = V + (size_t)bh * SEQ * DIM;
    float* Op = O + ((size_t)bh * SEQ + q0) * DIM;

    __shared__ float Ps[QB][KB + 4];
    __shared__ float Vs[KB][DIM + 8];   // pad 8 -> conflict-free B-frag reads
    __shared__ float invs[QB];

    const int tid  = threadIdx.x;
    const int warp = tid >> 5;
    const int lane = tid & 31;
    const int gr   = lane >> 2;
    const int lc   = lane & 3;

    if (tid < QB) invs[tid] = g_invsum[bh * SEQ + q0 + tid];

    float acc[8][4];
#pragma unroll
    for (int nt = 0; nt < 8; nt++) { acc[nt][0] = acc[nt][1] = acc[nt][2] = acc[nt][3] = 0.f; }

    for (int kt = 0; kt < SEQ / KB; kt++) {
        __syncthreads();   // also orders invs[] before first use

        // Load P tile, normalize, write final attention back, stage tf32 in smem.
        for (int i = tid; i < QB * (KB / 4); i += 128) {
            int r = i >> 4, c4 = (i & 15) << 2;
            float* pp = Pp + (size_t)r * SEQ + kt * KB + c4;
            float4 p = *reinterpret_cast<float4*>(pp);
            float inv = invs[r];
            p.x *= inv; p.y *= inv; p.z *= inv; p.w *= inv;
            *reinterpret_cast<float4*>(pp) = p;
            Ps[r][c4 + 0] = __uint_as_float(f2tf32(p.x));
            Ps[r][c4 + 1] = __uint_as_float(f2tf32(p.y));
            Ps[r][c4 + 2] = __uint_as_float(f2tf32(p.z));
            Ps[r][c4 + 3] = __uint_as_float(f2tf32(p.w));
        }
        // Load V tile.
        const float* Vt = Vp + (size_t)kt * KB * DIM;
        for (int i = tid; i < KB * (DIM / 4); i += 128) {
            int r = i >> 4, c4 = (i & 15) << 2;
            float4 v = *reinterpret_cast<const float4*>(Vt + (size_t)r * DIM + c4);
            Vs[r][c4 + 0] = __uint_as_float(f2tf32(v.x));
            Vs[r][c4 + 1] = __uint_as_float(f2tf32(v.y));
            Vs[r][c4 + 2] = __uint_as_float(f2tf32(v.z));
            Vs[r][c4 + 3] = __uint_as_float(f2tf32(v.w));
        }
        __syncthreads();

#pragma unroll
        for (int ks = 0; ks < 8; ks++) {
            unsigned af[4];
            af[0] = __float_as_uint(Ps[warp * 16 + gr    ][ks * 8 + lc    ]);
            af[1] = __float_as_uint(Ps[warp * 16 + gr + 8][ks * 8 + lc    ]);
            af[2] = __float_as_uint(Ps[warp * 16 + gr    ][ks * 8 + lc + 4]);
            af[3] = __float_as_uint(Ps[warp * 16 + gr + 8][ks * 8 + lc + 4]);
#pragma unroll
            for (int nt = 0; nt < 8; nt++) {
                // B fragment: b0 = B[k=lc][n=gr] = V[ks*8+lc][nt*8+gr]
                unsigned b0 = __float_as_uint(Vs[ks * 8 + lc    ][nt * 8 + gr]);
                unsigned b1 = __float_as_uint(Vs[ks * 8 + lc + 4][nt * 8 + gr]);
                mma_tf32(acc[nt], af, b0, b1);
            }
        }
    }

    // Write O.
#pragma unroll
    for (int nt = 0; nt < 8; nt++) {
        int col = nt * 8 + lc * 2;
        *reinterpret_cast<float2*>(Op + (size_t)(warp * 16 + gr) * DIM + col) =
            make_float2(acc[nt][0], acc[nt][1]);
        *reinterpret_cast<float2*>(Op + (size_t)(warp * 16 + gr + 8) * DIM + col) =
            make_float2(acc[nt][2], acc[nt][3]);
    }
}

// ===========================================================================
extern "C" void kernel_launch(void* const* d_in, const int* in_sizes, int n_in,
                              void* d_out, int out_size) {
    (void)in_sizes; (void)n_in; (void)out_size;
    const float* Q   = (const float*)d_in[0];
    const float* K   = (const float*)d_in[1];
    const float* V   = (const float*)d_in[2];
    const int*  mask = (const int*)d_in[3];

    // Output layout: [output (B*H*S*D) | attention (B*H*S*S)]
    float* O = (float*)d_out;
    float* P = (float*)d_out + (size_t)NBH * SEQ * DIM;

    dim3 grid(SEQ / QB, NBH);
    qk_exp_kernel<<<grid, 128>>>(Q, K, mask, P);
    av_kernel<<<grid, 128>>>(V, P, O);
}

// round 7
// speedup vs baseline: 2.0827x; 2.0827x over previous
#include <cuda_runtime.h>
#include <cstdint>

#define SEQ   4096
#define DIM   64
#define NBH   16          // B*H
#define QB    64
#define KB    64
#define NT    (SEQ/KB)    // 64 key tiles
#define MW    (SEQ/32)    // packed mask words per row
#define SCALE 0.125f      // 1/sqrt(64)

// Packed mask bits (2 MB, L2-resident). Written by pack_mask_kernel each call.
__device__ unsigned g_pmask[SEQ * MW];

__device__ __forceinline__ unsigned f2tf32(float f) {
    unsigned u;
    asm("cvt.rna.tf32.f32 %0, %1;" : "=r"(u) : "f"(f));
    return u;
}
__device__ __forceinline__ float tf32f(float f) { return __uint_as_float(f2tf32(f)); }

__device__ __forceinline__ void mma_tf32(float c[4], const unsigned a[4],
                                         unsigned b0, unsigned b1) {
    asm volatile(
        "mma.sync.aligned.m16n8k8.row.col.f32.tf32.tf32.f32 "
        "{%0,%1,%2,%3}, {%4,%5,%6,%7}, {%8,%9}, {%0,%1,%2,%3};\n"
        : "+f"(c[0]), "+f"(c[1]), "+f"(c[2]), "+f"(c[3])
        : "r"(a[0]), "r"(a[1]), "r"(a[2]), "r"(a[3]), "r"(b0), "r"(b1));
}

__device__ __forceinline__ void cp_async16(void* dst, const void* src) {
    unsigned s = (unsigned)__cvta_generic_to_shared(dst);
    asm volatile("cp.async.ca.shared.global [%0], [%1], 16;\n" :: "r"(s), "l"(src));
}
#define CP_COMMIT() asm volatile("cp.async.commit_group;\n")

// ===========================================================================
// Mask bit-packing: one ballot per 32 ints. ONE THREAD PER MASK ELEMENT.
// ===========================================================================
__global__ __launch_bounds__(256) void pack_mask_kernel(const int* __restrict__ mask) {
    int g = blockIdx.x * 256 + threadIdx.x;
    unsigned b = __ballot_sync(0xffffffffu, mask[g] != 0);
    if ((threadIdx.x & 31) == 0) g_pmask[g >> 5] = b;
}

// ===========================================================================
// Fused attention. Per CTA: 64 queries x all 4096 keys, 4 warps.
// Pass A: rowsums of exp(masked scores). Pass B: recompute, write normalized
// P once, accumulate O = Pn @ V.
// ===========================================================================
__global__ __launch_bounds__(128) void attn_fused_kernel(
    const float* __restrict__ Q, const float* __restrict__ Kg,
    const float* __restrict__ Vg, float* __restrict__ P, float* __restrict__ O)
{
    const int bh = blockIdx.y;
    const int q0 = blockIdx.x * QB;
    const float* Qp = Q  + ((size_t)bh * SEQ + q0) * DIM;
    const float* Kp = Kg + (size_t)bh * SEQ * DIM;
    const float* Vp = Vg + (size_t)bh * SEQ * DIM;
    float* Pp = P + ((size_t)bh * SEQ + q0) * SEQ;
    float* Op = O + ((size_t)bh * SEQ + q0) * DIM;

    // Dynamic smem: Ks[2][64][68] then Vs[2][64][72]
    extern __shared__ float smem[];
    float (*Ks)[KB][DIM + 4] = reinterpret_cast<float (*)[KB][DIM + 4]>(smem);
    float (*Vs)[KB][DIM + 8] = reinterpret_cast<float (*)[KB][DIM + 8]>(smem + 2 * KB * (DIM + 4));

    const int tid  = threadIdx.x;
    const int warp = tid >> 5;
    const int lane = tid & 31;
    const int gr   = lane >> 2;
    const int lc   = lane & 3;
    const int qg0  = q0 + warp * 16 + gr;

    // ---- Stage Q into Ks[0], pre-scaled + tf32-rounded; hoist A fragments.
#pragma unroll
    for (int it = 0; it < 8; it++) {
        int j = tid + it * 128;
        int r = j >> 4, cc = (j & 15) << 2;
        float4 v = *reinterpret_cast<const float4*>(Qp + (size_t)r * DIM + cc);
        Ks[0][r][cc + 0] = tf32f(v.x * SCALE);
        Ks[0][r][cc + 1] = tf32f(v.y * SCALE);
        Ks[0][r][cc + 2] = tf32f(v.z * SCALE);
        Ks[0][r][cc + 3] = tf32f(v.w * SCALE);
    }
    __syncthreads();
    unsigned a[8][4];
#pragma unroll
    for (int ds = 0; ds < 8; ds++) {
        a[ds][0] = __float_as_uint(Ks[0][warp * 16 + gr    ][ds * 8 + lc    ]);
        a[ds][1] = __float_as_uint(Ks[0][warp * 16 + gr + 8][ds * 8 + lc    ]);
        a[ds][2] = __float_as_uint(Ks[0][warp * 16 + gr    ][ds * 8 + lc + 4]);
        a[ds][3] = __float_as_uint(Ks[0][warp * 16 + gr + 8][ds * 8 + lc + 4]);
    }
    __syncthreads();

    // Async tile loaders (raw fp32; mma truncates B to tf32 in HW).
    auto issueK = [&](int kt, int buf) {
        const float* Kt = Kp + (size_t)kt * KB * DIM;
#pragma unroll
        for (int it = 0; it < 8; it++) {
            int j = tid + it * 128;
            int r = j >> 4, cc = (j & 15) << 2;
            cp_async16(&Ks[buf][r][cc], Kt + (size_t)r * DIM + cc);
        }
    };
    auto issueV = [&](int kt, int buf) {
        const float* Vt = Vp + (size_t)kt * KB * DIM;
#pragma unroll
        for (int it = 0; it < 8; it++) {
            int j = tid + it * 128;
            int r = j >> 4, cc = (j & 15) << 2;
            cp_async16(&Vs[buf][r][cc], Vt + (size_t)r * DIM + cc);
        }
    };

    // =========================== PASS A: row sums ===========================
    float rs0 = 0.f, rs1 = 0.f;
    issueK(0, 0); CP_COMMIT();

    for (int kt = 0; kt < NT; kt++) {
        const int cur = kt & 1;
        if (kt + 1 < NT) { issueK(kt + 1, cur ^ 1); CP_COMMIT(); }
        // packed mask words for this kt (rows qg0, qg0+8; cols kt*64..+63)
        const unsigned* pm = g_pmask + (size_t)qg0 * MW + kt * 2;
        unsigned w0a = pm[0], w0b = pm[1];
        unsigned w1a = pm[8 * MW], w1b = pm[8 * MW + 1];
        if (kt + 1 < NT) asm volatile("cp.async.wait_group 1;\n");
        else             asm volatile("cp.async.wait_group 0;\n");
        __syncthreads();

        float c[8][4];
#pragma unroll
        for (int nt = 0; nt < 8; nt++) { c[nt][0]=c[nt][1]=c[nt][2]=c[nt][3]=0.f; }
#pragma unroll
        for (int ds = 0; ds < 8; ds++) {
#pragma unroll
            for (int nt = 0; nt < 8; nt++) {
                unsigned b0 = __float_as_uint(Ks[cur][nt * 8 + gr][ds * 8 + lc    ]);
                unsigned b1 = __float_as_uint(Ks[cur][nt * 8 + gr][ds * 8 + lc + 4]);
                mma_tf32(c[nt], a[ds], b0, b1);
            }
        }
#pragma unroll
        for (int nt = 0; nt < 8; nt++) {
            int colb = nt * 8 + lc * 2;
            unsigned wa = (nt < 4) ? w0a : w0b;
            unsigned wb = (nt < 4) ? w1a : w1b;
            int sh = colb & 31;
            float e0 = ((wa >> sh) & 1u)       ? __expf(c[nt][0]) : 0.f;
            float e1 = ((wa >> (sh + 1)) & 1u) ? __expf(c[nt][1]) : 0.f;
            float e2 = ((wb >> sh) & 1u)       ? __expf(c[nt][2]) : 0.f;
            float e3 = ((wb >> (sh + 1)) & 1u) ? __expf(c[nt][3]) : 0.f;
            rs0 += e0 + e1;
            rs1 += e2 + e3;
        }
        __syncthreads();
    }

    rs0 += __shfl_xor_sync(0xffffffffu, rs0, 1);
    rs0 += __shfl_xor_sync(0xffffffffu, rs0, 2);
    rs1 += __shfl_xor_sync(0xffffffffu, rs1, 1);
    rs1 += __shfl_xor_sync(0xffffffffu, rs1, 2);
    const float inv0 = 1.f / rs0;
    const float inv1 = 1.f / rs1;

    // ======================= PASS B: write P, O = Pn@V ======================
    float acc[8][4];
#pragma unroll
    for (int vt = 0; vt < 8; vt++) { acc[vt][0]=acc[vt][1]=acc[vt][2]=acc[vt][3]=0.f; }

    issueK(0, 0); issueV(0, 0); CP_COMMIT();

    const int L0 = (gr << 2) | (lc >> 1);
    const int L2v = L0 + 2;
    const bool odd = (lc & 1);

    for (int kt = 0; kt < NT; kt++) {
        const int cur = kt & 1;
        if (kt + 1 < NT) { issueK(kt + 1, cur ^ 1); issueV(kt + 1, cur ^ 1); CP_COMMIT(); }
        const unsigned* pm = g_pmask + (size_t)qg0 * MW + kt * 2;
        unsigned w0a = pm[0], w0b = pm[1];
        unsigned w1a = pm[8 * MW], w1b = pm[8 * MW + 1];
        if (kt + 1 < NT) asm volatile("cp.async.wait_group 1;\n");
        else             asm volatile("cp.async.wait_group 0;\n");
        __syncthreads();

        float c[8][4];
#pragma unroll
        for (int nt = 0; nt < 8; nt++) { c[nt][0]=c[nt][1]=c[nt][2]=c[nt][3]=0.f; }
#pragma unroll
        for (int ds = 0; ds < 8; ds++) {
#pragma unroll
            for (int nt = 0; nt < 8; nt++) {
                unsigned b0 = __float_as_uint(Ks[cur][nt * 8 + gr][ds * 8 + lc    ]);
                unsigned b1 = __float_as_uint(Ks[cur][nt * 8 + gr][ds * 8 + lc + 4]);
                mma_tf32(c[nt], a[ds], b0, b1);
            }
        }

#pragma unroll
        for (int nt = 0; nt < 8; nt++) {
            int colb = nt * 8 + lc * 2;
            unsigned wa = (nt < 4) ? w0a : w0b;
            unsigned wb = (nt < 4) ? w1a : w1b;
            int sh = colb & 31;
            float p0 = ((wa >> sh) & 1u)       ? __expf(c[nt][0]) * inv0 : 0.f;
            float p1 = ((wa >> (sh + 1)) & 1u) ? __expf(c[nt][1]) * inv0 : 0.f;
            float p2 = ((wb >> sh) & 1u)       ? __expf(c[nt][2]) * inv1 : 0.f;
            float p3 = ((wb >> (sh + 1)) & 1u) ? __expf(c[nt][3]) * inv1 : 0.f;

            // final attention store (normalized, fp32, written exactly once)
            int col = kt * KB + colb;
            *reinterpret_cast<float2*>(Pp + (size_t)(warp * 16 + gr    ) * SEQ + col) =
                make_float2(p0, p1);
            *reinterpret_cast<float2*>(Pp + (size_t)(warp * 16 + gr + 8) * SEQ + col) =
                make_float2(p2, p3);

            // C-fragment -> A-fragment (within-warp shuffles)
            float y0 = __shfl_sync(0xffffffffu, p0, L0);
            float y1 = __shfl_sync(0xffffffffu, p1, L0);
            float y2 = __shfl_sync(0xffffffffu, p2, L0);
            float y3 = __shfl_sync(0xffffffffu, p3, L0);
            float z0 = __shfl_sync(0xffffffffu, p0, L2v);
            float z1 = __shfl_sync(0xffffffffu, p1, L2v);
            float z2 = __shfl_sync(0xffffffffu, p2, L2v);
            float z3 = __shfl_sync(0xffffffffu, p3, L2v);
            unsigned afr[4];
            afr[0] = f2tf32(odd ? y1 : y0);
            afr[1] = f2tf32(odd ? y3 : y2);
            afr[2] = f2tf32(odd ? z1 : z0);
            afr[3] = f2tf32(odd ? z3 : z2);

#pragma unroll
            for (int vt = 0; vt < 8; vt++) {
                unsigned b0 = __float_as_uint(Vs[cur][nt * 8 + lc    ][vt * 8 + gr]);
                unsigned b1 = __float_as_uint(Vs[cur][nt * 8 + lc + 4][vt * 8 + gr]);
                mma_tf32(acc[vt], afr, b0, b1);
            }
        }
        __syncthreads();
    }

    // ---- Write O (already normalized).
#pragma unroll
    for (int vt = 0; vt < 8; vt++) {
        int col = vt * 8 + lc * 2;
        *reinterpret_cast<float2*>(Op + (size_t)(warp * 16 + gr    ) * DIM + col) =
            make_float2(acc[vt][0], acc[vt][1]);
        *reinterpret_cast<float2*>(Op + (size_t)(warp * 16 + gr + 8) * DIM + col) =
            make_float2(acc[vt][2], acc[vt][3]);
    }
}

// ===========================================================================
extern "C" void kernel_launch(void* const* d_in, const int* in_sizes, int n_in,
                              void* d_out, int out_size) {
    (void)in_sizes; (void)n_in; (void)out_size;
    const float* Q   = (const float*)d_in[0];
    const float* K   = (const float*)d_in[1];
    const float* V   = (const float*)d_in[2];
    const int*  mask = (const int*)d_in[3];

    float* O = (float*)d_out;
    float* P = (float*)d_out + (size_t)NBH * SEQ * DIM;

    const int smem_bytes = (2 * KB * (DIM + 4) + 2 * KB * (DIM + 8)) * sizeof(float); // 71680
    cudaFuncSetAttribute(attn_fused_kernel,
                         cudaFuncAttributeMaxDynamicSharedMemorySize, smem_bytes);

    // FIXED (R6 bug): one thread per mask element -> (SEQ*SEQ)/256 = 65536 blocks.
    pack_mask_kernel<<<(SEQ * SEQ) / 256, 256>>>(mask);

    attn_fused_kernel<<<dim3(SEQ / QB, NBH), 128, smem_bytes>>>(Q, K, V, P, O);
}

// round 9
// speedup vs baseline: 2.4696x; 1.1858x over previous
#include <cuda_runtime.h>
#include <cstdint>

#define SEQ   4096
#define DIM   64
#define NBH   16          // B*H
#define QB    64
#define KB    64
#define NT    (SEQ/KB)    // 64 key tiles
#define MW    (SEQ/32)    // packed mask words per row
// scale * log2(e): scores computed directly in log2 domain for ex2.approx
#define SCALE_L2E 0.1803368801111204f

#define KRS 72            // K smem row stride (floats): conflict-free LDS.64
#define VRS 64            // V smem row stride (floats): swizzled, no pad

// Scratch (allocation-free per harness rules).
__device__ unsigned g_pmask[SEQ * MW];
__device__ float g_Kr[NBH * SEQ * DIM];   // rna tf32, column-permuted for LDS.64 pairs
__device__ float g_Vr[NBH * SEQ * DIM];   // rna tf32, col-permuted + XOR chunk swizzle

__device__ __forceinline__ unsigned f2tf32(float f) {
    unsigned u;
    asm("cvt.rna.tf32.f32 %0, %1;" : "=r"(u) : "f"(f));
    return u;
}
__device__ __forceinline__ float tf32f(float f) { return __uint_as_float(f2tf32(f)); }

__device__ __forceinline__ float ex2(float x) {
    float y;
    asm("ex2.approx.f32 %0, %1;" : "=f"(y) : "f"(x));
    return y;
}

__device__ __forceinline__ void mma_tf32(float c[4], const unsigned a[4],
                                         unsigned b0, unsigned b1) {
    asm volatile(
        "mma.sync.aligned.m16n8k8.row.col.f32.tf32.tf32.f32 "
        "{%0,%1,%2,%3}, {%4,%5,%6,%7}, {%8,%9}, {%0,%1,%2,%3};\n"
        : "+f"(c[0]), "+f"(c[1]), "+f"(c[2]), "+f"(c[3])
        : "r"(a[0]), "r"(a[1]), "r"(a[2]), "r"(a[3]), "r"(b0), "r"(b1));
}

__device__ __forceinline__ void cp_async16(void* dst, const void* src) {
    unsigned s = (unsigned)__cvta_generic_to_shared(dst);
    asm volatile("cp.async.cg.shared.global [%0], [%1], 16;\n" :: "r"(s), "l"(src));
}
#define CP_COMMIT() asm volatile("cp.async.commit_group;\n")

// ===========================================================================
// Prep kernels
// ===========================================================================
__global__ __launch_bounds__(256) void pack_mask_kernel(const int* __restrict__ mask) {
    int g = blockIdx.x * 256 + threadIdx.x;
    unsigned b = __ballot_sync(0xffffffffu, mask[g] != 0);
    if ((threadIdx.x & 31) == 0) g_pmask[g >> 5] = b;
}

// K: rna round + column permutation  p = ds*8 + 2*lc + h  <-  c_in = ds*8 + lc + 4*h
__global__ __launch_bounds__(256) void prep_k_kernel(const float* __restrict__ K) {
    int o = blockIdx.x * 256 + threadIdx.x;          // output element index
    int p = o & (DIM - 1);
    int rowbase = o - p;
    int ds = p >> 3, t = p & 7;
    int lc = t >> 1, h = t & 1;
    int c_in = ds * 8 + lc + 4 * h;
    g_Kr[o] = tf32f(K[rowbase + c_in]);
}

// V: rna round + col permutation (vt*8+gr -> gr*8+vt) + per-row XOR chunk swizzle
__global__ __launch_bounds__(256) void prep_v_kernel(const float* __restrict__ V) {
    int o = blockIdx.x * 256 + threadIdx.x;
    int p = o & (DIM - 1);
    int row = (o >> 6);                               // global row index
    int r3 = row & 3;
    int gsw = (r3 & 1) | ((r3 & 2) << 1);             // 0,1,4,5
    int chunkp = p >> 2, within = p & 3;
    int chunk = chunkp ^ gsw;                         // logical chunk
    int f = chunk * 4 + within;                       // logical permuted col
    int gr = f >> 3, vt = f & 7;
    int c_in = vt * 8 + gr;
    g_Vr[o] = tf32f(V[(o - p) + c_in]);
}

// ===========================================================================
// Fused attention. Per CTA: 64 queries x all 4096 keys, 4 warps.
// ===========================================================================
__global__ __launch_bounds__(128) void attn_fused_kernel(
    const float* __restrict__ Q, float* __restrict__ P, float* __restrict__ O)
{
    const int bh = blockIdx.y;
    const int q0 = blockIdx.x * QB;
    const float* Qp = Q + ((size_t)bh * SEQ + q0) * DIM;
    const float* Kp = g_Kr + (size_t)bh * SEQ * DIM;
    const float* Vp = g_Vr + (size_t)bh * SEQ * DIM;
    float* Pp = P + ((size_t)bh * SEQ + q0) * SEQ;
    float* Op = O + ((size_t)bh * SEQ + q0) * DIM;

    // smem: Ks[2][64][72] (36.9KB) then Vs[2][64][64] (32.8KB)
    extern __shared__ float smem[];
    float (*Ks)[KB][KRS] = reinterpret_cast<float (*)[KB][KRS]>(smem);
    float (*Vs)[KB][VRS] = reinterpret_cast<float (*)[KB][VRS]>(smem + 2 * KB * KRS);

    const int tid  = threadIdx.x;
    const int warp = tid >> 5;
    const int lane = tid & 31;
    const int gr   = lane >> 2;
    const int lc   = lane & 3;
    const int qg0  = q0 + warp * 16 + gr;
    const int gsw  = (lc & 1) | ((lc & 2) << 1);   // V chunk swizzle key

    // ---- Stage Q into Ks[0] (plain layout, stride KRS); hoist A fragments.
#pragma unroll
    for (int it = 0; it < 8; it++) {
        int j = tid + it * 128;
        int r = j >> 4, cc = (j & 15) << 2;
        float4 v = *reinterpret_cast<const float4*>(Qp + (size_t)r * DIM + cc);
        Ks[0][r][cc + 0] = tf32f(v.x * SCALE_L2E);
        Ks[0][r][cc + 1] = tf32f(v.y * SCALE_L2E);
        Ks[0][r][cc + 2] = tf32f(v.z * SCALE_L2E);
        Ks[0][r][cc + 3] = tf32f(v.w * SCALE_L2E);
    }
    __syncthreads();
    unsigned a[8][4];
#pragma unroll
    for (int ds = 0; ds < 8; ds++) {
        a[ds][0] = __float_as_uint(Ks[0][warp * 16 + gr    ][ds * 8 + lc    ]);
        a[ds][1] = __float_as_uint(Ks[0][warp * 16 + gr + 8][ds * 8 + lc    ]);
        a[ds][2] = __float_as_uint(Ks[0][warp * 16 + gr    ][ds * 8 + lc + 4]);
        a[ds][3] = __float_as_uint(Ks[0][warp * 16 + gr + 8][ds * 8 + lc + 4]);
    }
    __syncthreads();

    auto issueK = [&](int kt, int buf) {
        const float* Kt = Kp + (size_t)kt * KB * DIM;
#pragma unroll
        for (int it = 0; it < 8; it++) {
            int j = tid + it * 128;
            int r = j >> 4, cc = (j & 15) << 2;
            cp_async16(&Ks[buf][r][cc], Kt + (size_t)r * DIM + cc);
        }
    };
    auto issueV = [&](int kt, int buf) {
        const float* Vt = Vp + (size_t)kt * KB * DIM;
#pragma unroll
        for (int it = 0; it < 8; it++) {
            int j = tid + it * 128;
            int r = j >> 4, cc = (j & 15) << 2;
            cp_async16(&Vs[buf][r][cc], Vt + (size_t)r * DIM + cc);
        }
    };

    // =========================== PASS A: row sums ===========================
    float rs0 = 0.f, rs1 = 0.f;
    issueK(0, 0); CP_COMMIT();

    for (int kt = 0; kt < NT; kt++) {
        const int cur = kt & 1;
        if (kt + 1 < NT) { issueK(kt + 1, cur ^ 1); CP_COMMIT(); }
        const unsigned* pm = g_pmask + (size_t)qg0 * MW + kt * 2;
        unsigned w0a = pm[0], w0b = pm[1];
        unsigned w1a = pm[8 * MW], w1b = pm[8 * MW + 1];
        if (kt + 1 < NT) asm volatile("cp.async.wait_group 1;\n");
        else             asm volatile("cp.async.wait_group 0;\n");
        __syncthreads();

        float c[8][4];
#pragma unroll
        for (int nt = 0; nt < 8; nt++) { c[nt][0]=c[nt][1]=c[nt][2]=c[nt][3]=0.f; }
#pragma unroll
        for (int ds = 0; ds < 8; ds++) {
#pragma unroll
            for (int nt = 0; nt < 8; nt++) {
                float2 kv = *reinterpret_cast<const float2*>(
                    &Ks[cur][nt * 8 + gr][ds * 8 + 2 * lc]);
                mma_tf32(c[nt], a[ds], __float_as_uint(kv.x), __float_as_uint(kv.y));
            }
        }
#pragma unroll
        for (int nt = 0; nt < 8; nt++) {
            int colb = nt * 8 + lc * 2;
            unsigned wa = (nt < 4) ? w0a : w0b;
            unsigned wb = (nt < 4) ? w1a : w1b;
            int sh = colb & 31;
            float e0 = ((wa >> sh) & 1u)       ? ex2(c[nt][0]) : 0.f;
            float e1 = ((wa >> (sh + 1)) & 1u) ? ex2(c[nt][1]) : 0.f;
            float e2 = ((wb >> sh) & 1u)       ? ex2(c[nt][2]) : 0.f;
            float e3 = ((wb >> (sh + 1)) & 1u) ? ex2(c[nt][3]) : 0.f;
            rs0 += e0 + e1;
            rs1 += e2 + e3;
        }
        __syncthreads();
    }

    rs0 += __shfl_xor_sync(0xffffffffu, rs0, 1);
    rs0 += __shfl_xor_sync(0xffffffffu, rs0, 2);
    rs1 += __shfl_xor_sync(0xffffffffu, rs1, 1);
    rs1 += __shfl_xor_sync(0xffffffffu, rs1, 2);
    const float inv0 = 1.f / rs0;
    const float inv1 = 1.f / rs1;

    // ======================= PASS B: write P, O = Pn@V ======================
    float acc[8][4];
#pragma unroll
    for (int vt = 0; vt < 8; vt++) { acc[vt][0]=acc[vt][1]=acc[vt][2]=acc[vt][3]=0.f; }

    issueK(0, 0); issueV(0, 0); CP_COMMIT();

    const int L0 = (gr << 2) | (lc >> 1);
    const int L2v = L0 + 2;
    const bool odd = (lc & 1);

    for (int kt = 0; kt < NT; kt++) {
        const int cur = kt & 1;
        if (kt + 1 < NT) { issueK(kt + 1, cur ^ 1); issueV(kt + 1, cur ^ 1); CP_COMMIT(); }
        const unsigned* pm = g_pmask + (size_t)qg0 * MW + kt * 2;
        unsigned w0a = pm[0], w0b = pm[1];
        unsigned w1a = pm[8 * MW], w1b = pm[8 * MW + 1];
        if (kt + 1 < NT) asm volatile("cp.async.wait_group 1;\n");
        else             asm volatile("cp.async.wait_group 0;\n");
        __syncthreads();

        float c[8][4];
#pragma unroll
        for (int nt = 0; nt < 8; nt++) { c[nt][0]=c[nt][1]=c[nt][2]=c[nt][3]=0.f; }
#pragma unroll
        for (int ds = 0; ds < 8; ds++) {
#pragma unroll
            for (int nt = 0; nt < 8; nt++) {
                float2 kv = *reinterpret_cast<const float2*>(
                    &Ks[cur][nt * 8 + gr][ds * 8 + 2 * lc]);
                mma_tf32(c[nt], a[ds], __float_as_uint(kv.x), __float_as_uint(kv.y));
            }
        }

#pragma unroll
        for (int nt = 0; nt < 8; nt++) {
            int colb = nt * 8 + lc * 2;
            unsigned wa = (nt < 4) ? w0a : w0b;
            unsigned wb = (nt < 4) ? w1a : w1b;
            int sh = colb & 31;
            float p0 = ((wa >> sh) & 1u)       ? ex2(c[nt][0]) * inv0 : 0.f;
            float p1 = ((wa >> (sh + 1)) & 1u) ? ex2(c[nt][1]) * inv0 : 0.f;
            float p2 = ((wb >> sh) & 1u)       ? ex2(c[nt][2]) * inv1 : 0.f;
            float p3 = ((wb >> (sh + 1)) & 1u) ? ex2(c[nt][3]) * inv1 : 0.f;

            // final attention store (normalized, streaming hint)
            int col = kt * KB + colb;
            __stcs(reinterpret_cast<float2*>(Pp + (size_t)(warp * 16 + gr    ) * SEQ + col),
                   make_float2(p0, p1));
            __stcs(reinterpret_cast<float2*>(Pp + (size_t)(warp * 16 + gr + 8) * SEQ + col),
                   make_float2(p2, p3));

            // C-fragment -> A-fragment (within-warp shuffles)
            float y0 = __shfl_sync(0xffffffffu, p0, L0);
            float y1 = __shfl_sync(0xffffffffu, p1, L0);
            float y2 = __shfl_sync(0xffffffffu, p2, L0);
            float y3 = __shfl_sync(0xffffffffu, p3, L0);
            float z0 = __shfl_sync(0xffffffffu, p0, L2v);
            float z1 = __shfl_sync(0xffffffffu, p1, L2v);
            float z2 = __shfl_sync(0xffffffffu, p2, L2v);
            float z3 = __shfl_sync(0xffffffffu, p3, L2v);
            unsigned afr[4];
            afr[0] = f2tf32(odd ? y1 : y0);
            afr[1] = f2tf32(odd ? y3 : y2);
            afr[2] = f2tf32(odd ? z1 : z0);
            afr[3] = f2tf32(odd ? z3 : z2);

            // V fragments: swizzled LDS.128 (4 per nt instead of 16 LDS.32)
            const float* vrow0 = &Vs[cur][nt * 8 + lc    ][0];
            const float* vrow1 = &Vs[cur][nt * 8 + lc + 4][0];
            float4 A0 = *reinterpret_cast<const float4*>(vrow0 + (((2*gr  ) ^ gsw) << 2));
            float4 A1 = *reinterpret_cast<const float4*>(vrow0 + (((2*gr+1) ^ gsw) << 2));
            float4 B0 = *reinterpret_cast<const float4*>(vrow1 + (((2*gr  ) ^ gsw) << 2));
            float4 B1 = *reinterpret_cast<const float4*>(vrow1 + (((2*gr+1) ^ gsw) << 2));

            mma_tf32(acc[0], afr, __float_as_uint(A0.x), __float_as_uint(B0.x));
            mma_tf32(acc[1], afr, __float_as_uint(A0.y), __float_as_uint(B0.y));
            mma_tf32(acc[2], afr, __float_as_uint(A0.z), __float_as_uint(B0.z));
            mma_tf32(acc[3], afr, __float_as_uint(A0.w), __float_as_uint(B0.w));
            mma_tf32(acc[4], afr, __float_as_uint(A1.x), __float_as_uint(B1.x));
            mma_tf32(acc[5], afr, __float_as_uint(A1.y), __float_as_uint(B1.y));
            mma_tf32(acc[6], afr, __float_as_uint(A1.z), __float_as_uint(B1.z));
            mma_tf32(acc[7], afr, __float_as_uint(A1.w), __float_as_uint(B1.w));
        }
        __syncthreads();
    }

    // ---- Write O. acc[vt] columns are PERMUTED (logical col vt*8+gr stored
    // in acc order gr*8+vt). Thread owns output cols: for acc[j], register c
    // pair: cols handled below map back: acc index j corresponds to V logical
    // column (j<4 ? A-group : ...) -- recover original col = ( (j&3) + (j>>2)*4 )?
    // Careful: acc[j] used b from permuted col f = 2*gr*4 + j (j<4) or (2*gr+1)*4 + (j-4)
    //   f = gr*8 + j  (for j 0..7, since A0/A1 are chunks 2gr,2gr+1 pre-unswizzle)
    //   original V col = vt*8 + gr' where f = gr'*8 + vt -> gr' = gr, vt = j.
    // So acc[j] holds output col block vt=j, i.e., cols j*8 + (n-index of mma).
    // mma n-dim for AV: columns of V tile -> n = 8 lanes mapping: c regs cols 2lc,2lc+1
    //   within the 8-wide block vt*8.. -> same as before: col = vt*8 + 2*lc (+1).
#pragma unroll
    for (int vt = 0; vt < 8; vt++) {
        int col = vt * 8 + lc * 2;
        *reinterpret_cast<float2*>(Op + (size_t)(warp * 16 + gr    ) * DIM + col) =
            make_float2(acc[vt][0], acc[vt][1]);
        *reinterpret_cast<float2*>(Op + (size_t)(warp * 16 + gr + 8) * DIM + col) =
            make_float2(acc[vt][2], acc[vt][3]);
    }
}

// ===========================================================================
extern "C" void kernel_launch(void* const* d_in, const int* in_sizes, int n_in,
                              void* d_out, int out_size) {
    (void)in_sizes; (void)n_in; (void)out_size;
    const float* Q   = (const float*)d_in[0];
    const float* K   = (const float*)d_in[1];
    const float* V   = (const float*)d_in[2];
    const int*  mask = (const int*)d_in[3];

    float* O = (float*)d_out;
    float* P = (float*)d_out + (size_t)NBH * SEQ * DIM;

    const int smem_bytes = (2 * KB * KRS + 2 * KB * VRS) * sizeof(float); // 69632
    cudaFuncSetAttribute(attn_fused_kernel,
                         cudaFuncAttributeMaxDynamicSharedMemorySize, smem_bytes);

    pack_mask_kernel<<<(SEQ * SEQ) / 256, 256>>>(mask);
    prep_k_kernel<<<(NBH * SEQ * DIM) / 256, 256>>>(K);
    prep_v_kernel<<<(NBH * SEQ * DIM) / 256, 256>>>(V);

    attn_fused_kernel<<<dim3(SEQ / QB, NBH), 128, smem_bytes>>>(Q, P, O);
}